// round 6
// baseline (speedup 1.0000x reference)
#include <cuda_runtime.h>
#include <cooperative_groups.h>
#include <math.h>

namespace cg = cooperative_groups;

#define ROW_LEN   65536
#define CSIZE     8
#define SEG       (ROW_LEN / CSIZE)     // 8192 elements per CTA
#define THREADS   256
#define TPT       32                    // thread owns [base, base+32)
#define HALO      5
#define JOFF      8

#define TREND_SCALING       0.6f
#define DETAIL_PRESERVATION 0.85f
#define SPIKE_THRESHOLD     3.5f
#define SPIKE_DAMPING       0.35f
#define EPS_STD             1e-6f

// XOR swizzle: permutes 16B quads within 128B rows; per-lane stride of 32
// floats (1 row) makes every float4 LDS/STS phase conflict-free.
__device__ __forceinline__ int SX(int j) { return j ^ ((j >> 3) & 0x1C); }

// smem layout (floats)
#define OFF_RED     8224                // 17 floats: warp partials + thr
#define OFF_MAIL    8244                // 16 floats: per-rank (s, ss)
#define SMEM_FLOATS 8260
#define SMEM_BYTES  (SMEM_FLOATS * 4)

// element accessor over the register window: i in [-5, 36]
#define E(i) ((i) < 0 ? hl[(i) + 5] : ((i) >= TPT ? hr[(i) - TPT] : v[(i)]))

__global__ void __launch_bounds__(THREADS, 4) __cluster_dims__(CSIZE, 1, 1)
fd6_kernel(const float* __restrict__ x, float* __restrict__ out)
{
    extern __shared__ float sm[];
    float* red  = sm + OFF_RED;
    float* mail = sm + OFF_MAIL;

    cg::cluster_group cl = cg::this_cluster();
    const int rank = (int)cl.block_rank();
    const int row  = blockIdx.x / CSIZE;
    const int tid  = threadIdx.x;
    const int lane = tid & 31;
    const size_t gbase = (size_t)row * ROW_LEN + (size_t)rank * SEG;
    const int base = tid * TPT;

    // ---- stage segment into swizzled smem (coalesced LDG.128 -> STS.128) ----
    {
        const float4* gx = reinterpret_cast<const float4*>(x + gbase);
        #pragma unroll
        for (int g = 0; g < SEG / (THREADS * 4); g++) {     // 8
            int q = g * (THREADS * 4) + tid * 4;
            float4 t = gx[q >> 2];
            *reinterpret_cast<float4*>(sm + SX(JOFF + q)) = t;
        }
    }

    for (int iter = 0; iter < 2; iter++) {
        cl.sync();   // data (stage or iter-0 stores) visible cluster-wide

        // ---- cluster/edge halo cells in smem (5 left, 5 right) ----
        if (tid < HALO) {
            int d = tid + 1;                 // 1..5
            float lv;
            if (rank == 0) {
                lv = sm[SX(JOFF + d)];                       // reflect -d -> d
            } else {
                const float* peer = cl.map_shared_rank(sm, rank - 1);
                lv = peer[SX(JOFF + SEG - d)];
            }
            sm[SX(JOFF - d)] = lv;

            int k = tid;                     // 0..4
            float rv;
            if (rank == CSIZE - 1) {
                rv = sm[SX(JOFF + SEG - 2 - k)];             // reflect L+k -> L-2-k
            } else {
                const float* peer = cl.map_shared_rank(sm, rank + 1);
                rv = peer[SX(JOFF + k)];
            }
            sm[SX(JOFF + SEG + k)] = rv;
        }
        __syncthreads();

        // ---- single smem read: v[32] = elements [base, base+32) ----
        float v[TPT];
        #pragma unroll
        for (int i = 0; i < TPT / 4; i++) {
            float4 t = *reinterpret_cast<const float4*>(sm + SX(JOFF + base + i * 4));
            v[i * 4 + 0] = t.x; v[i * 4 + 1] = t.y;
            v[i * 4 + 2] = t.z; v[i * 4 + 3] = t.w;
        }

        // ---- halo regs: shfl from neighbor lanes; warp edges read smem ----
        const unsigned m = 0xffffffffu;
        float hl[HALO], hr[HALO];
        #pragma unroll
        for (int k = 0; k < HALO; k++) {
            hl[k] = __shfl_up_sync(m, v[TPT - HALO + k], 1);   // elem base-5+k
            hr[k] = __shfl_down_sync(m, v[k], 1);              // elem base+32+k
        }
        if (lane == 0) {
            #pragma unroll
            for (int k = 0; k < HALO; k++)
                hl[k] = sm[SX(JOFF + base - HALO + k)];
        }
        if (lane == 31) {
            #pragma unroll
            for (int k = 0; k < HALO; k++)
                hr[k] = sm[SX(JOFF + base + TPT + k)];
        }

        // ---- stats: sum/sumsq of residual = cur - box5(cur) ----
        float s = 0.f, ss = 0.f;
        {
            float s5 = E(-2) + E(-1) + E(0) + E(1) + E(2);
            #pragma unroll
            for (int o = 0; o < TPT; o++) {
                if (o) s5 += E(o + 2) - E(o - 3);
                float r = v[o] - 0.2f * s5;
                s += r;  ss += r * r;
            }
        }

        // ---- block reduce (deterministic) ----
        #pragma unroll
        for (int off = 16; off; off >>= 1) {
            s  += __shfl_down_sync(m, s,  off);
            ss += __shfl_down_sync(m, ss, off);
        }
        const int wid = tid >> 5;
        if (lane == 0) { red[wid] = s; red[8 + wid] = ss; }
        __syncthreads();

        // ---- PUSH partials into every CTA's mailbox (incl. own) ----
        if (tid == 0) {
            float bs = 0.f, bss = 0.f;
            #pragma unroll
            for (int w = 0; w < 8; w++) { bs += red[w]; bss += red[8 + w]; }
            #pragma unroll
            for (int r2 = 0; r2 < CSIZE; r2++) {
                float* pm = cl.map_shared_rank(sm, r2) + OFF_MAIL;
                pm[2 * rank]     = bs;
                pm[2 * rank + 1] = bss;
            }
        }
        cl.sync();   // pushes visible; all CTAs' old-value reads complete
                     // cluster-wide before any store below

        // ---- local mailbox reduce, fixed rank order ----
        if (tid == 0) {
            float cs = 0.f, css = 0.f;
            #pragma unroll
            for (int r2 = 0; r2 < CSIZE; r2++) {
                cs  += mail[2 * r2];
                css += mail[2 * r2 + 1];
            }
            const float n = (float)ROW_LEN;
            float var = (css - cs * cs / n) / (n - 1.0f);
            var = fmaxf(var, 0.0f);
            float sc = fmaxf(sqrtf(var), EPS_STD);
            red[16] = sc * SPIKE_THRESHOLD;
        }
        __syncthreads();
        const float thr = red[16];

        // ---- update from registers only; store in-place (iter0) / global ----
        {
            float s5  = E(-2) + E(-1) + E(0) + E(1) + E(2);
            float s11 = E(-5) + E(-4) + E(-3) + E(-2) + E(-1) + E(0) +
                        E(1) + E(2) + E(3) + E(4) + E(5);
            #pragma unroll
            for (int i = 0; i < TPT / 4; i++) {
                float4 t4;
                float* tp = reinterpret_cast<float*>(&t4);
                #pragma unroll
                for (int q = 0; q < 4; q++) {
                    int o = i * 4 + q;
                    if (o) {
                        s5  += E(o + 2) - E(o - 3);
                        s11 += E(o + 5) - E(o - 6);
                    }
                    float r = v[o] - 0.2f * s5;
                    float f = (fabsf(r) > thr)
                                  ? (DETAIL_PRESERVATION * SPIKE_DAMPING)
                                  : DETAIL_PRESERVATION;
                    float c = fmaf(s5, (1.0f - TREND_SCALING) * 0.2f,
                                   s11 * (TREND_SCALING / 11.0f));
                    tp[q] = fmaf(r, f, c);
                }
                if (iter == 0) {
                    *reinterpret_cast<float4*>(sm + SX(JOFF + base + i * 4)) = t4;
                } else {
                    *reinterpret_cast<float4*>(out + gbase + base + i * 4) = t4;
                }
            }
        }
    }

    // lifetime: no CTA exits while a peer may still touch its SMEM
    cl.sync();
}

extern "C" void kernel_launch(void* const* d_in, const int* in_sizes, int n_in,
                              void* d_out, int out_size)
{
    const float* x = (const float*)d_in[0];
    float* out = (float*)d_out;
    const int rows = in_sizes[0] / ROW_LEN;   // 512

    cudaFuncSetAttribute(fd6_kernel,
                         cudaFuncAttributeMaxDynamicSharedMemorySize, SMEM_BYTES);
    fd6_kernel<<<rows * CSIZE, THREADS, SMEM_BYTES>>>(x, out);
}

// round 7
// speedup vs baseline: 1.0920x; 1.0920x over previous
#include <cuda_runtime.h>
#include <cooperative_groups.h>
#include <math.h>

namespace cg = cooperative_groups;

#define ROW_LEN   65536
#define CSIZE     8
#define SEG       (ROW_LEN / CSIZE)     // 8192 elements per CTA
#define THREADS   256
#define TPT       32                    // thread streams [base, base+32)
#define JOFF      8

#define TREND_SCALING       0.6f
#define DETAIL_PRESERVATION 0.85f
#define SPIKE_THRESHOLD     3.5f
#define SPIKE_DAMPING       0.35f
#define EPS_STD             1e-6f
#define F_KEEP   DETAIL_PRESERVATION                      // 0.85
#define F_DAMP   (DETAIL_PRESERVATION * SPIKE_DAMPING)    // 0.2975
#define C5       ((1.0f - TREND_SCALING) * 0.2f)          // 0.08
#define C11      (TREND_SCALING / 11.0f)

// XOR swizzle: permutes quads within 128B rows by row index; all float4
// LDS/STS at per-lane stride 32 floats are bank-conflict-free.
__device__ __forceinline__ int SX(int j) { return j ^ ((j >> 3) & 0x1C); }

// smem layout (floats): data cells j in [0, 8224), then scratch
#define OFF_RED     8224                // 17 floats: warp partials + thr
#define OFF_MAIL    8244                // 16 floats: per-rank (s, ss)
#define SMEM_FLOATS 8260
#define SMEM_BYTES  (SMEM_FLOATS * 4)

__device__ __forceinline__ float4 LD4(const float* sm, int j) {
    return *reinterpret_cast<const float4*>(sm + SX(j));
}
__device__ __forceinline__ void ST4(float* sm, int j, float4 v) {
    *reinterpret_cast<float4*>(sm + SX(j)) = v;
}

__global__ void __launch_bounds__(THREADS, 5) __cluster_dims__(CSIZE, 1, 1)
fd7_kernel(const float* __restrict__ x, float* __restrict__ out)
{
    extern __shared__ float sm[];
    float* red  = sm + OFF_RED;
    float* mail = sm + OFF_MAIL;

    cg::cluster_group cl = cg::this_cluster();
    const int rank = (int)cl.block_rank();
    const int row  = blockIdx.x / CSIZE;
    const int tid  = threadIdx.x;
    const size_t gbase = (size_t)row * ROW_LEN + (size_t)rank * SEG;
    const int base = JOFF + tid * TPT;   // smem cell index of element 0 of this thread

    // ---- stage segment into swizzled smem (coalesced LDG.128 -> STS.128) ----
    {
        const float4* gx = reinterpret_cast<const float4*>(x + gbase);
        #pragma unroll
        for (int g = 0; g < SEG / (THREADS * 4); g++) {     // 8
            int q = g * (THREADS * 4) + tid * 4;
            ST4(sm, JOFF + q, gx[q >> 2]);
        }
    }

    for (int iter = 0; iter < 2; iter++) {
        cl.sync();   // data (stage or iter-0 stores) visible cluster-wide

        // ---- halo cells: 8 left / 8 right (5 meaningful + zero pad) ----
        if (tid < 8) {
            int d = 8 - tid;                 // 8..1 ; cell e[-d]
            float lv = 0.f;
            if (d <= 5) {
                if (rank == 0) {
                    lv = sm[SX(JOFF + d)];                   // reflect -d -> d
                } else {
                    const float* peer = cl.map_shared_rank(sm, rank - 1);
                    lv = peer[SX(JOFF + SEG - d)];
                }
            }
            sm[SX(JOFF - d)] = lv;

            int k = tid;                     // 0..7 ; cell e[SEG+k]
            float rv = 0.f;
            if (k <= 4) {
                if (rank == CSIZE - 1) {
                    rv = sm[SX(JOFF + SEG - 2 - k)];         // reflect L+k -> L-2-k
                } else {
                    const float* peer = cl.map_shared_rank(sm, rank + 1);
                    rv = peer[SX(JOFF + k)];
                }
            }
            sm[SX(JOFF + SEG + k)] = rv;
        }
        __syncthreads();

        // ---- stats stream: sum/sumsq of residual = cur - box5(cur) ----
        float s = 0.f, ss = 0.f;
        {
            float4 p = LD4(sm, base - 4);
            float4 c = LD4(sm, base);
            float t2 = p.z, t3 = p.w;                // e[-2], e[-1]
            float s5 = t2 + t3 + c.x + c.y + c.z;    // window center 0
            #pragma unroll
            for (int k = 0; k < 8; k++) {
                float4 n = LD4(sm, base + 4 * k + 4);
                float r;
                r = c.x - 0.2f * s5; s += r; ss += r * r;
                s5 += c.w - t2;
                r = c.y - 0.2f * s5; s += r; ss += r * r;
                s5 += n.x - t3;
                r = c.z - 0.2f * s5; s += r; ss += r * r;
                s5 += n.y - c.x;
                r = c.w - 0.2f * s5; s += r; ss += r * r;
                s5 += n.z - c.y;
                t2 = c.z; t3 = c.w;
                c = n;
            }
        }

        // ---- block reduce (deterministic order) ----
        const unsigned m = 0xffffffffu;
        #pragma unroll
        for (int off = 16; off; off >>= 1) {
            s  += __shfl_down_sync(m, s,  off);
            ss += __shfl_down_sync(m, ss, off);
        }
        const int wid = tid >> 5, lid = tid & 31;
        if (lid == 0) { red[wid] = s; red[8 + wid] = ss; }
        __syncthreads();

        // ---- PUSH partials into every CTA's mailbox (incl. own) ----
        if (tid == 0) {
            float bs = 0.f, bss = 0.f;
            #pragma unroll
            for (int w = 0; w < 8; w++) { bs += red[w]; bss += red[8 + w]; }
            #pragma unroll
            for (int r2 = 0; r2 < CSIZE; r2++) {
                float* pm = cl.map_shared_rank(sm, r2) + OFF_MAIL;
                pm[2 * rank]     = bs;
                pm[2 * rank + 1] = bss;
            }
        }
        cl.sync();   // pushes visible; all cross-CTA reads complete before stores

        // ---- local mailbox reduce, fixed rank order (identical everywhere) ----
        if (tid == 0) {
            float cs = 0.f, css = 0.f;
            #pragma unroll
            for (int r2 = 0; r2 < CSIZE; r2++) {
                cs  += mail[2 * r2];
                css += mail[2 * r2 + 1];
            }
            const float n = (float)ROW_LEN;
            float var = (css - cs * cs / n) / (n - 1.0f);
            var = fmaxf(var, 0.0f);
            float sc = fmaxf(sqrtf(var), EPS_STD);
            red[16] = sc * SPIKE_THRESHOLD;
        }
        __syncthreads();
        const float thr = red[16];

        // ---- update stream ----
        // Preload the 4 cross-thread overlap quads (old values), then barrier,
        // then stream own region: read quad j at step j-2, write at step j.
        float4 lm = LD4(sm, base - 8);
        float4 l  = LD4(sm, base - 4);
        float4 r6 = LD4(sm, base + 32);
        float4 r7 = LD4(sm, base + 36);
        if (iter == 0) __syncthreads();   // all cross-thread reads done

        float4 a = LD4(sm, base);         // quad [0,4)
        float4 b = LD4(sm, base + 4);     // quad [4,8)
        float4 qm1 = l;                   // quad [-4,0)
        float  em5 = lm.w;                // e[-5]
        float  s5  = l.z + l.w + a.x + a.y + a.z;
        float  s11 = lm.w + l.x + l.y + l.z + l.w +
                     a.x + a.y + a.z + a.w + b.x + b.y;

        float4* go = reinterpret_cast<float4*>(out + gbase + tid * TPT);

        #pragma unroll
        for (int k = 0; k < 8; k++) {
            float4 n = (k < 6) ? LD4(sm, base + 4 * k + 8)
                               : ((k == 6) ? r6 : r7);
            float4 o4;
            float r, f, cc;

            r  = a.x - 0.2f * s5;
            f  = (fabsf(r) > thr) ? F_DAMP : F_KEEP;
            cc = fmaf(s5, C5, s11 * C11);
            o4.x = fmaf(r, f, cc);
            s5  += a.w - qm1.z;   s11 += b.z - em5;

            r  = a.y - 0.2f * s5;
            f  = (fabsf(r) > thr) ? F_DAMP : F_KEEP;
            cc = fmaf(s5, C5, s11 * C11);
            o4.y = fmaf(r, f, cc);
            s5  += b.x - qm1.w;   s11 += b.w - qm1.x;

            r  = a.z - 0.2f * s5;
            f  = (fabsf(r) > thr) ? F_DAMP : F_KEEP;
            cc = fmaf(s5, C5, s11 * C11);
            o4.z = fmaf(r, f, cc);
            s5  += b.y - a.x;     s11 += n.x - qm1.y;

            r  = a.w - 0.2f * s5;
            f  = (fabsf(r) > thr) ? F_DAMP : F_KEEP;
            cc = fmaf(s5, C5, s11 * C11);
            o4.w = fmaf(r, f, cc);
            s5  += b.z - a.y;     s11 += n.y - qm1.z;

            if (iter == 0) ST4(sm, base + 4 * k, o4);
            else           go[k] = o4;

            em5 = qm1.w;
            qm1 = a; a = b; b = n;
        }
    }

    // lifetime: no CTA exits while a peer may still touch its SMEM
    cl.sync();
}

extern "C" void kernel_launch(void* const* d_in, const int* in_sizes, int n_in,
                              void* d_out, int out_size)
{
    const float* x = (const float*)d_in[0];
    float* out = (float*)d_out;
    const int rows = in_sizes[0] / ROW_LEN;   // 512

    cudaFuncSetAttribute(fd7_kernel,
                         cudaFuncAttributeMaxDynamicSharedMemorySize, SMEM_BYTES);
    fd7_kernel<<<rows * CSIZE, THREADS, SMEM_BYTES>>>(x, out);
}

// round 8
// speedup vs baseline: 1.1154x; 1.0214x over previous
#include <cuda_runtime.h>
#include <cooperative_groups.h>
#include <math.h>

namespace cg = cooperative_groups;

#define ROW_LEN   65536
#define CSIZE     8
#define SEG       (ROW_LEN / CSIZE)     // 8192 elements per CTA
#define THREADS   256
#define TPT       32                    // thread streams [base, base+32)
#define JOFF      8

#define TREND_SCALING       0.6f
#define DETAIL_PRESERVATION 0.85f
#define SPIKE_THRESHOLD     3.5f
#define SPIKE_DAMPING       0.35f
#define EPS_STD             1e-6f
#define F_KEEP   DETAIL_PRESERVATION                      // 0.85
#define F_DAMP   (DETAIL_PRESERVATION * SPIKE_DAMPING)    // 0.2975
#define C5       ((1.0f - TREND_SCALING) * 0.2f)          // 0.08
#define C11      (TREND_SCALING / 11.0f)

// XOR swizzle: permutes quads within 128B rows by row index; all float4
// LDS/STS at per-lane stride of 32 floats are bank-conflict-free.
__device__ __forceinline__ int SX(int j) { return j ^ ((j >> 3) & 0x1C); }

// smem layout (floats): data cells j in [0, 8224), then scratch
#define OFF_RED     8224                // 17 floats: warp partials + thr
#define OFF_MAIL    8244                // 16 floats: per-rank (s, ss)
#define SMEM_FLOATS 8260
#define SMEM_BYTES  (SMEM_FLOATS * 4)

__device__ __forceinline__ float4 LD4(const float* sm, int j) {
    return *reinterpret_cast<const float4*>(sm + SX(j));
}
__device__ __forceinline__ void ST4(float* sm, int j, float4 v) {
    *reinterpret_cast<float4*>(sm + SX(j)) = v;
}

__global__ void __launch_bounds__(THREADS, 4) __cluster_dims__(CSIZE, 1, 1)
fd8b_kernel(const float* __restrict__ x, float* __restrict__ out)
{
    extern __shared__ float sm[];
    float* red  = sm + OFF_RED;
    float* mail = sm + OFF_MAIL;

    cg::cluster_group cl = cg::this_cluster();
    const int rank = (int)cl.block_rank();
    const int row  = blockIdx.x / CSIZE;
    const int tid  = threadIdx.x;
    const size_t gbase = (size_t)row * ROW_LEN + (size_t)rank * SEG;
    const int base = JOFF + tid * TPT;   // smem cell of this thread's element 0

    // ---- stage segment into swizzled smem (coalesced LDG.128 -> STS.128) ----
    {
        const float4* gx = reinterpret_cast<const float4*>(x + gbase);
        #pragma unroll
        for (int g = 0; g < SEG / (THREADS * 4); g++) {     // 8
            int q = g * (THREADS * 4) + tid * 4;
            ST4(sm, JOFF + q, gx[q >> 2]);
        }
    }

    for (int iter = 0; iter < 2; iter++) {
        cl.sync();   // data (stage or iter-0 stores) visible cluster-wide

        // ---- halo cells: 8 left / 8 right (5 meaningful + zero pad) ----
        if (tid < 8) {
            int d = 8 - tid;                 // 8..1 ; cell e[-d]
            float lv = 0.f;
            if (d <= 5) {
                if (rank == 0) {
                    lv = sm[SX(JOFF + d)];                   // reflect -d -> d
                } else {
                    const float* peer = cl.map_shared_rank(sm, rank - 1);
                    lv = peer[SX(JOFF + SEG - d)];
                }
            }
            sm[SX(JOFF - d)] = lv;

            int k = tid;                     // 0..7 ; cell e[SEG+k]
            float rv = 0.f;
            if (k <= 4) {
                if (rank == CSIZE - 1) {
                    rv = sm[SX(JOFF + SEG - 2 - k)];         // reflect L+k -> L-2-k
                } else {
                    const float* peer = cl.map_shared_rank(sm, rank + 1);
                    rv = peer[SX(JOFF + k)];
                }
            }
            sm[SX(JOFF + SEG + k)] = rv;
        }
        __syncthreads();

        // ---- stats stream: sum/sumsq of residual = cur - box5(cur) ----
        float s = 0.f, ss = 0.f;
        {
            float4 p = LD4(sm, base - 4);
            float4 c = LD4(sm, base);
            float t2 = p.z, t3 = p.w;                // e[-2], e[-1]
            float s5 = t2 + t3 + c.x + c.y + c.z;
            #pragma unroll
            for (int k = 0; k < 8; k++) {
                float4 n = LD4(sm, base + 4 * k + 4);
                float r;
                r = c.x - 0.2f * s5; s += r; ss += r * r;
                s5 += c.w - t2;
                r = c.y - 0.2f * s5; s += r; ss += r * r;
                s5 += n.x - t3;
                r = c.z - 0.2f * s5; s += r; ss += r * r;
                s5 += n.y - c.x;
                r = c.w - 0.2f * s5; s += r; ss += r * r;
                s5 += n.z - c.y;
                t2 = c.z; t3 = c.w;
                c = n;
            }
        }

        // ---- block reduce (deterministic order) ----
        const unsigned m = 0xffffffffu;
        #pragma unroll
        for (int off = 16; off; off >>= 1) {
            s  += __shfl_down_sync(m, s,  off);
            ss += __shfl_down_sync(m, ss, off);
        }
        const int wid = tid >> 5, lid = tid & 31;
        if (lid == 0) { red[wid] = s; red[8 + wid] = ss; }
        __syncthreads();

        // ---- PUSH partials into every CTA's mailbox (incl. own) ----
        if (tid == 0) {
            float bs = 0.f, bss = 0.f;
            #pragma unroll
            for (int w = 0; w < 8; w++) { bs += red[w]; bss += red[8 + w]; }
            #pragma unroll
            for (int r2 = 0; r2 < CSIZE; r2++) {
                float* pm = cl.map_shared_rank(sm, r2) + OFF_MAIL;
                pm[2 * rank]     = bs;
                pm[2 * rank + 1] = bss;
            }
        }
        cl.sync();   // pushes visible; all cross-CTA reads complete before stores

        // ---- local mailbox reduce, fixed rank order (identical everywhere) ----
        if (tid == 0) {
            float cs = 0.f, css = 0.f;
            #pragma unroll
            for (int r2 = 0; r2 < CSIZE; r2++) {
                cs  += mail[2 * r2];
                css += mail[2 * r2 + 1];
            }
            const float n = (float)ROW_LEN;
            float var = (css - cs * cs / n) / (n - 1.0f);
            var = fmaxf(var, 0.0f);
            float sc = fmaxf(sqrtf(var), EPS_STD);
            red[16] = sc * SPIKE_THRESHOLD;
        }
        __syncthreads();
        const float thr = red[16];

        // ---- update stream ----
        // iter 0 (in-place): preload overlap values (old), barrier, then stream
        // with reads 2 quads ahead of writes. iter 1: no hazard, all in-stream.
        float  em5 = sm[SX(base - 5)];
        float4 l   = LD4(sm, base - 4);
        float4 r6, r7;
        if (iter == 0) {
            r6 = LD4(sm, base + 32);
            r7 = LD4(sm, base + 36);
            __syncthreads();   // all cross-thread old-value reads done
        }

        float4 a = LD4(sm, base);         // quad [0,4)
        float4 b = LD4(sm, base + 4);     // quad [4,8)
        float4 qm1 = l;                   // quad [-4,0)
        float  s5  = l.z + l.w + a.x + a.y + a.z;
        float  s11 = em5 + l.x + l.y + l.z + l.w +
                     a.x + a.y + a.z + a.w + b.x + b.y;

        float4* go = reinterpret_cast<float4*>(out + gbase + tid * TPT);

        #pragma unroll
        for (int k = 0; k < 8; k++) {
            float4 n;
            if (iter == 0) n = (k < 6) ? LD4(sm, base + 4 * k + 8)
                                       : ((k == 6) ? r6 : r7);
            else           n = LD4(sm, base + 4 * k + 8);

            float4 o4;
            float r, f, cc;

            r  = a.x - 0.2f * s5;
            f  = (fabsf(r) > thr) ? F_DAMP : F_KEEP;
            cc = fmaf(s5, C5, s11 * C11);
            o4.x = fmaf(r, f, cc);
            s5  += a.w - qm1.z;   s11 += b.z - em5;

            r  = a.y - 0.2f * s5;
            f  = (fabsf(r) > thr) ? F_DAMP : F_KEEP;
            cc = fmaf(s5, C5, s11 * C11);
            o4.y = fmaf(r, f, cc);
            s5  += b.x - qm1.w;   s11 += b.w - qm1.x;

            r  = a.z - 0.2f * s5;
            f  = (fabsf(r) > thr) ? F_DAMP : F_KEEP;
            cc = fmaf(s5, C5, s11 * C11);
            o4.z = fmaf(r, f, cc);
            s5  += b.y - a.x;     s11 += n.x - qm1.y;

            r  = a.w - 0.2f * s5;
            f  = (fabsf(r) > thr) ? F_DAMP : F_KEEP;
            cc = fmaf(s5, C5, s11 * C11);
            o4.w = fmaf(r, f, cc);
            s5  += b.z - a.y;     s11 += n.y - qm1.z;

            if (iter == 0) ST4(sm, base + 4 * k, o4);
            else           go[k] = o4;

            em5 = qm1.w;
            qm1 = a; a = b; b = n;
        }
    }

    // lifetime: no CTA exits while a peer may still touch its SMEM
    cl.sync();
}

extern "C" void kernel_launch(void* const* d_in, const int* in_sizes, int n_in,
                              void* d_out, int out_size)
{
    const float* x = (const float*)d_in[0];
    float* out = (float*)d_out;
    const int rows = in_sizes[0] / ROW_LEN;   // 512

    cudaFuncSetAttribute(fd8b_kernel,
                         cudaFuncAttributeMaxDynamicSharedMemorySize, SMEM_BYTES);
    fd8b_kernel<<<rows * CSIZE, THREADS, SMEM_BYTES>>>(x, out);
}